// round 11
// baseline (speedup 1.0000x reference)
#include <cuda_runtime.h>

#define B_   32
#define C_   256
#define H_   64
#define W_   64
#define HW_  4096            // H*W
#define BC_  8192            // B*C
#define HID_ 64
#define KSZ_ 5

#define CHUNK_B 16           // batches per chunk (64 MB of x, fits L2)
#define NCHUNK  (B_ / CHUNK_B)
#define RPC_    (CHUNK_B * C_)   // rows per chunk = 4096

// Scratch (allocation-free rule: __device__ globals)
__device__ float g_mean[BC_];
__device__ float g_h4v[BC_];    // 0.125 / (var + 1e-4)
__device__ float g_s2[BC_];     // sum over HW of x*sigmoid(energy)

__device__ __forceinline__ float sigm(float v) {          // tiny gate math only
    return 1.0f / (1.0f + __expf(-v));
}
__device__ __forceinline__ float tanh_fast(float v) {     // MUFU.TANH, 1 MUFU
    float r;
    asm("tanh.approx.f32 %0, %1;" : "=f"(r) : "f"(v));
    return r;
}

struct F8 { float4 a, b; };    // 32-byte vector

// 32-byte load pinned into L2 with lowest eviction priority (sm_103a: v4.b64)
__device__ __forceinline__ F8 ldg32_evict_last(const void* p) {
    unsigned long long r0, r1, r2, r3;
    asm volatile("ld.global.L2::evict_last.v4.b64 {%0,%1,%2,%3}, [%4];"
                 : "=l"(r0), "=l"(r1), "=l"(r2), "=l"(r3) : "l"(p));
    F8 v;
    v.a.x = __uint_as_float((unsigned)(r0));
    v.a.y = __uint_as_float((unsigned)(r0 >> 32));
    v.a.z = __uint_as_float((unsigned)(r1));
    v.a.w = __uint_as_float((unsigned)(r1 >> 32));
    v.b.x = __uint_as_float((unsigned)(r2));
    v.b.y = __uint_as_float((unsigned)(r2 >> 32));
    v.b.z = __uint_as_float((unsigned)(r3));
    v.b.w = __uint_as_float((unsigned)(r3 >> 32));
    return v;
}

// ---------------------------------------------------------------------------
// Kernel 1: per-(b,c) stats + SimAM-weighted sum for one 16-batch chunk.
// evict_last reads pin the 64 MB chunk in L2 for the out pass.
// ---------------------------------------------------------------------------
__global__ void __launch_bounds__(256, 8) stat_kernel(const float* __restrict__ x,
                                                      int b0)
{
    const int row = b0 * C_ + blockIdx.x;
    const int t   = threadIdx.x;
    const float* xr = x + (size_t)row * HW_;

    F8 v[2];
#pragma unroll
    for (int j = 0; j < 2; j++) v[j] = ldg32_evict_last(xr + t * 8 + j * 2048);

    float s = 0.f, ss = 0.f;
#pragma unroll
    for (int j = 0; j < 2; j++) {
        float4 q = v[j].a;
        s  += (q.x + q.y) + (q.z + q.w);
        ss += q.x * q.x + q.y * q.y + q.z * q.z + q.w * q.w;
        q = v[j].b;
        s  += (q.x + q.y) + (q.z + q.w);
        ss += q.x * q.x + q.y * q.y + q.z * q.z + q.w * q.w;
    }
#pragma unroll
    for (int o = 16; o > 0; o >>= 1) {
        s  += __shfl_xor_sync(0xffffffffu, s,  o);
        ss += __shfl_xor_sync(0xffffffffu, ss, o);
    }

    __shared__ float shS[8], shQ[8], bcast[2];
    const int w = t >> 5, l = t & 31;
    if (l == 0) { shS[w] = s; shQ[w] = ss; }
    __syncthreads();
    if (t == 0) {
        float S = 0.f, Q = 0.f;
#pragma unroll
        for (int i = 0; i < 8; i++) { S += shS[i]; Q += shQ[i]; }
        const float mean = S * (1.0f / HW_);
        const float var  = (Q - (float)HW_ * mean * mean) * (1.0f / (HW_ - 1));
        const float h4v  = 0.125f / (var + 1e-4f);
        bcast[0] = mean; bcast[1] = h4v;
        g_mean[row] = mean;
        g_h4v[row]  = h4v;
    }
    __syncthreads();
    const float mean = bcast[0];
    const float h4v  = bcast[1];

    float s2 = 0.f;
#pragma unroll
    for (int j = 0; j < 2; j++) {
        float d, th;
        float4 q = v[j].a;
        d = q.x - mean; th = tanh_fast(fmaf(d * d, h4v, 0.25f)); s2 = fmaf(q.x, fmaf(th, 0.5f, 0.5f), s2);
        d = q.y - mean; th = tanh_fast(fmaf(d * d, h4v, 0.25f)); s2 = fmaf(q.y, fmaf(th, 0.5f, 0.5f), s2);
        d = q.z - mean; th = tanh_fast(fmaf(d * d, h4v, 0.25f)); s2 = fmaf(q.z, fmaf(th, 0.5f, 0.5f), s2);
        d = q.w - mean; th = tanh_fast(fmaf(d * d, h4v, 0.25f)); s2 = fmaf(q.w, fmaf(th, 0.5f, 0.5f), s2);
        q = v[j].b;
        d = q.x - mean; th = tanh_fast(fmaf(d * d, h4v, 0.25f)); s2 = fmaf(q.x, fmaf(th, 0.5f, 0.5f), s2);
        d = q.y - mean; th = tanh_fast(fmaf(d * d, h4v, 0.25f)); s2 = fmaf(q.y, fmaf(th, 0.5f, 0.5f), s2);
        d = q.z - mean; th = tanh_fast(fmaf(d * d, h4v, 0.25f)); s2 = fmaf(q.z, fmaf(th, 0.5f, 0.5f), s2);
        d = q.w - mean; th = tanh_fast(fmaf(d * d, h4v, 0.25f)); s2 = fmaf(q.w, fmaf(th, 0.5f, 0.5f), s2);
    }
#pragma unroll
    for (int o = 16; o > 0; o >>= 1)
        s2 += __shfl_xor_sync(0xffffffffu, s2, o);
    if (l == 0) shS[w] = s2;
    __syncthreads();
    if (t == 0) {
        float S = 0.f;
#pragma unroll
        for (int i = 0; i < 8; i++) S += shS[i];
        g_s2[row] = S;
    }
}

// ---------------------------------------------------------------------------
// Kernel 2: per-row out pass with the batch gate computed redundantly per CTA.
// All gate inputs (g_mean/g_s2 for the batch) are tiny L2-hit loads; the MLP2
// dot product is needed only for this CTA's own channel.
// x re-read hits L2 (64 MB chunk pinned by stat_kernel). Streaming stores.
// ---------------------------------------------------------------------------
__global__ void __launch_bounds__(256, 8) out_gate_kernel(const float* __restrict__ x,
                                                          const float* __restrict__ cw,
                                                          const float* __restrict__ w1,
                                                          const float* __restrict__ w2,
                                                          float* __restrict__ out,
                                                          int b0)
{
    const int row   = b0 * C_ + blockIdx.x;
    const int batch = row >> 8;
    const int crow  = row & (C_ - 1);
    const int t     = threadIdx.x;

    __shared__ float m[C_], gap[C_], gate_s[C_], hid[HID_];
    __shared__ float bc[2];                           // a2, a3

    // ---- gate (redundant per CTA, ~2 KB L2-hit input) ----
    m[t] = g_mean[batch * C_ + t];
    const float s2c = g_s2[batch * C_ + t];
    __syncthreads();

    float y = 0.f;
#pragma unroll
    for (int k = 0; k < KSZ_; k++) {
        const int cc = t + k - (KSZ_ - 1) / 2;
        const float mv = (cc >= 0 && cc < C_) ? m[cc] : 0.f;
        y = fmaf(mv, cw[k], y);
    }
    const float gate = sigm(y);
    gate_s[t] = gate;
    gap[t] = fmaf(gate, m[t], s2c * (1.0f / HW_));
    __syncthreads();

    {   // hid[j] = relu(sum_c gap[c]*w1[j,c]); 4 threads per j
        const int j = t >> 2, p = t & 3;
        float h = 0.f;
        const float* w1r = w1 + j * C_ + p * 64;
        const float* gp  = gap + p * 64;
#pragma unroll 8
        for (int i = 0; i < 64; i++) h = fmaf(gp[i], w1r[i], h);
        h += __shfl_xor_sync(0xffffffffu, h, 1);
        h += __shfl_xor_sync(0xffffffffu, h, 2);
        if (p == 0) hid[j] = fmaxf(h, 0.f);
    }
    __syncthreads();

    if (t < 32) {   // warp 0: alpha for THIS row's channel only
        float a = 0.f;
        const float* w2r = w2 + crow * HID_;
        a = fmaf(hid[t],      w2r[t],      a);
        a = fmaf(hid[t + 32], w2r[t + 32], a);
#pragma unroll
        for (int o = 16; o > 0; o >>= 1)
            a += __shfl_xor_sync(0xffffffffu, a, o);
        if (t == 0) {
            const float alpha = sigm(a);
            bc[0] = 0.5f * alpha;                          // a2
            bc[1] = fmaf(1.0f - alpha, gate_s[crow], bc[0]); // a3
        }
    }
    __syncthreads();

    const float mean = m[crow];
    const float h4v  = g_h4v[row];
    const float a2   = bc[0];
    const float a3   = bc[1];

    // ---- streamed row transform (reads = L2 hits) ----
    const float4* xr = (const float4*)(x   + (size_t)row * HW_);
    float4*       ow = (float4*)     (out + (size_t)row * HW_);

    float4 q[4];
#pragma unroll
    for (int j = 0; j < 4; j++) q[j] = xr[t + j * 256];

#pragma unroll
    for (int j = 0; j < 4; j++) {
        float d, th;
        d = q[j].x - mean; th = tanh_fast(fmaf(d * d, h4v, 0.25f)); q[j].x = q[j].x * fmaf(a2, th, a3);
        d = q[j].y - mean; th = tanh_fast(fmaf(d * d, h4v, 0.25f)); q[j].y = q[j].y * fmaf(a2, th, a3);
        d = q[j].z - mean; th = tanh_fast(fmaf(d * d, h4v, 0.25f)); q[j].z = q[j].z * fmaf(a2, th, a3);
        d = q[j].w - mean; th = tanh_fast(fmaf(d * d, h4v, 0.25f)); q[j].w = q[j].w * fmaf(a2, th, a3);
    }

#pragma unroll
    for (int j = 0; j < 4; j++) __stcs(&ow[t + j * 256], q[j]);
}

// ---------------------------------------------------------------------------
extern "C" void kernel_launch(void* const* d_in, const int* in_sizes, int n_in,
                              void* d_out, int out_size)
{
    const float* x  = (const float*)d_in[0];   // [B, C, H, W]
    const float* cw = (const float*)d_in[1];   // [1, 1, 5]
    const float* w1 = (const float*)d_in[2];   // [HID, C]
    const float* w2 = (const float*)d_in[3];   // [C, HID]
    float* out = (float*)d_out;

    for (int k = 0; k < NCHUNK; k++) {
        const int b0 = k * CHUNK_B;
        stat_kernel<<<RPC_, 256>>>(x, b0);
        out_gate_kernel<<<RPC_, 256>>>(x, cw, w1, w2, out, b0);
    }
}

// round 12
// speedup vs baseline: 5.3132x; 5.3132x over previous
#include <cuda_runtime.h>

#define B_   32
#define C_   256
#define H_   64
#define W_   64
#define HW_  4096            // H*W
#define BC_  8192            // B*C
#define HID_ 64
#define KSZ_ 5

#define CHUNK_B 16           // batches per chunk (64 MB of x, fits L2)
#define NCHUNK  (B_ / CHUNK_B)
#define RPC_    (CHUNK_B * C_)   // rows per chunk = 4096

// Scratch (allocation-free rule: __device__ globals)
__device__ float g_mean[BC_];
__device__ float g_h4v[BC_];    // 0.125 / (var + 1e-4)
__device__ float g_s2[BC_];     // sum over HW of x*sigmoid(energy)
__device__ float g_gate[BC_];   // ECA gate
__device__ float g_alpha[BC_];  // fusion gate

__device__ __forceinline__ float sigm(float v) {          // tiny gate math only
    return 1.0f / (1.0f + __expf(-v));
}
__device__ __forceinline__ float tanh_fast(float v) {     // MUFU.TANH, 1 MUFU
    float r;
    asm("tanh.approx.f32 %0, %1;" : "=f"(r) : "f"(v));
    return r;
}

struct F8 { float4 a, b; };    // 32-byte vector

// 32-byte load pinned into L2 with lowest eviction priority (sm_103a: v4.b64)
__device__ __forceinline__ F8 ldg32_evict_last(const void* p) {
    unsigned long long r0, r1, r2, r3;
    asm volatile("ld.global.L2::evict_last.v4.b64 {%0,%1,%2,%3}, [%4];"
                 : "=l"(r0), "=l"(r1), "=l"(r2), "=l"(r3) : "l"(p));
    F8 v;
    v.a.x = __uint_as_float((unsigned)(r0));
    v.a.y = __uint_as_float((unsigned)(r0 >> 32));
    v.a.z = __uint_as_float((unsigned)(r1));
    v.a.w = __uint_as_float((unsigned)(r1 >> 32));
    v.b.x = __uint_as_float((unsigned)(r2));
    v.b.y = __uint_as_float((unsigned)(r2 >> 32));
    v.b.z = __uint_as_float((unsigned)(r3));
    v.b.w = __uint_as_float((unsigned)(r3 >> 32));
    return v;
}

// ---------------------------------------------------------------------------
// Kernel 1: per-(b,c) stats + SimAM-weighted sum for one 16-batch chunk.
// evict_last reads pin the 64 MB chunk in L2 for the out pass.
// ---------------------------------------------------------------------------
__global__ void __launch_bounds__(256, 8) stat_kernel(const float* __restrict__ x,
                                                      int b0)
{
    const int row = b0 * C_ + blockIdx.x;
    const int t   = threadIdx.x;
    const float* xr = x + (size_t)row * HW_;

    F8 v[2];
#pragma unroll
    for (int j = 0; j < 2; j++) v[j] = ldg32_evict_last(xr + t * 8 + j * 2048);

    float s = 0.f, ss = 0.f;
#pragma unroll
    for (int j = 0; j < 2; j++) {
        float4 q = v[j].a;
        s  += (q.x + q.y) + (q.z + q.w);
        ss += q.x * q.x + q.y * q.y + q.z * q.z + q.w * q.w;
        q = v[j].b;
        s  += (q.x + q.y) + (q.z + q.w);
        ss += q.x * q.x + q.y * q.y + q.z * q.z + q.w * q.w;
    }
#pragma unroll
    for (int o = 16; o > 0; o >>= 1) {
        s  += __shfl_xor_sync(0xffffffffu, s,  o);
        ss += __shfl_xor_sync(0xffffffffu, ss, o);
    }

    __shared__ float shS[8], shQ[8], bcast[2];
    const int w = t >> 5, l = t & 31;
    if (l == 0) { shS[w] = s; shQ[w] = ss; }
    __syncthreads();
    if (t == 0) {
        float S = 0.f, Q = 0.f;
#pragma unroll
        for (int i = 0; i < 8; i++) { S += shS[i]; Q += shQ[i]; }
        const float mean = S * (1.0f / HW_);
        const float var  = (Q - (float)HW_ * mean * mean) * (1.0f / (HW_ - 1));
        const float h4v  = 0.125f / (var + 1e-4f);
        bcast[0] = mean; bcast[1] = h4v;
        g_mean[row] = mean;
        g_h4v[row]  = h4v;
    }
    __syncthreads();
    const float mean = bcast[0];
    const float h4v  = bcast[1];

    float s2 = 0.f;
#pragma unroll
    for (int j = 0; j < 2; j++) {
        float d, th;
        float4 q = v[j].a;
        d = q.x - mean; th = tanh_fast(fmaf(d * d, h4v, 0.25f)); s2 = fmaf(q.x, fmaf(th, 0.5f, 0.5f), s2);
        d = q.y - mean; th = tanh_fast(fmaf(d * d, h4v, 0.25f)); s2 = fmaf(q.y, fmaf(th, 0.5f, 0.5f), s2);
        d = q.z - mean; th = tanh_fast(fmaf(d * d, h4v, 0.25f)); s2 = fmaf(q.z, fmaf(th, 0.5f, 0.5f), s2);
        d = q.w - mean; th = tanh_fast(fmaf(d * d, h4v, 0.25f)); s2 = fmaf(q.w, fmaf(th, 0.5f, 0.5f), s2);
        q = v[j].b;
        d = q.x - mean; th = tanh_fast(fmaf(d * d, h4v, 0.25f)); s2 = fmaf(q.x, fmaf(th, 0.5f, 0.5f), s2);
        d = q.y - mean; th = tanh_fast(fmaf(d * d, h4v, 0.25f)); s2 = fmaf(q.y, fmaf(th, 0.5f, 0.5f), s2);
        d = q.z - mean; th = tanh_fast(fmaf(d * d, h4v, 0.25f)); s2 = fmaf(q.z, fmaf(th, 0.5f, 0.5f), s2);
        d = q.w - mean; th = tanh_fast(fmaf(d * d, h4v, 0.25f)); s2 = fmaf(q.w, fmaf(th, 0.5f, 0.5f), s2);
    }
#pragma unroll
    for (int o = 16; o > 0; o >>= 1)
        s2 += __shfl_xor_sync(0xffffffffu, s2, o);
    if (l == 0) shS[w] = s2;
    __syncthreads();
    if (t == 0) {
        float S = 0.f;
#pragma unroll
        for (int i = 0; i < 8; i++) S += shS[i];
        g_s2[row] = S;
    }
}

// ---------------------------------------------------------------------------
// Kernel 2: per-batch ECA conv + fusion MLP for one chunk. One CTA per batch.
// ---------------------------------------------------------------------------
__global__ void __launch_bounds__(256) gate_kernel(const float* __restrict__ cw,
                                                   const float* __restrict__ w1,
                                                   const float* __restrict__ w2,
                                                   int b0)
{
    const int b = b0 + blockIdx.x;
    const int c = threadIdx.x;        // 0..255
    const int idx = b * C_ + c;

    __shared__ float m[C_], gap[C_], hid[HID_];
    m[c] = g_mean[idx];
    __syncthreads();

    // ECA: cross-correlation over channel dim, zero-padded, K=5
    float y = 0.f;
#pragma unroll
    for (int k = 0; k < KSZ_; k++) {
        const int cc = c + k - (KSZ_ - 1) / 2;
        const float mv = (cc >= 0 && cc < C_) ? m[cc] : 0.f;
        y = fmaf(mv, cw[k], y);
    }
    const float gate = sigm(y);
    g_gate[idx] = gate;
    gap[c] = fmaf(gate, m[c], g_s2[idx] * (1.0f / HW_));
    __syncthreads();

    // hid[j] = relu(sum_c gap[c] * w1[j, c]); 4 threads per output j
    {
        const int j = c >> 2;          // 0..63
        const int p = c & 3;           // 0..3
        float h = 0.f;
        const float* w1r = w1 + j * C_ + p * 64;
        const float* gp  = gap + p * 64;
#pragma unroll 8
        for (int i = 0; i < 64; i++) h = fmaf(gp[i], w1r[i], h);
        h += __shfl_xor_sync(0xffffffffu, h, 1);
        h += __shfl_xor_sync(0xffffffffu, h, 2);
        if (p == 0) hid[j] = fmaxf(h, 0.f);
    }
    __syncthreads();

    // alpha[c] = sigmoid(sum_j hid[j] * w2[c, j]), w2 is [C, HID] row-major
    float a = 0.f;
    const float* w2r = w2 + c * HID_;
#pragma unroll 8
    for (int j = 0; j < HID_; j++) a = fmaf(hid[j], w2r[j], a);
    g_alpha[idx] = sigm(a);
}

// ---------------------------------------------------------------------------
// Kernel 3: out = x * (alpha*sigmoid(energy) + (1-alpha)*gate) for one chunk.
// x re-read hits L2 (64 MB chunk pinned by stat_kernel). Streaming stores.
// ---------------------------------------------------------------------------
__global__ void __launch_bounds__(256, 8) out_kernel(const float* __restrict__ x,
                                                     float* __restrict__ out,
                                                     int b0)
{
    const int row = b0 * C_ + blockIdx.x;
    const int t   = threadIdx.x;

    const float mean  = g_mean[row];
    const float h4v   = g_h4v[row];
    const float alpha = g_alpha[row];
    const float a2    = 0.5f * alpha;
    const float a3    = fmaf(1.0f - alpha, g_gate[row], a2);

    const float4* xr = (const float4*)(x   + (size_t)row * HW_);
    float4*       ow = (float4*)     (out + (size_t)row * HW_);

    float4 q[4];
#pragma unroll
    for (int j = 0; j < 4; j++) q[j] = xr[t + j * 256];

#pragma unroll
    for (int j = 0; j < 4; j++) {
        float d, th;
        d = q[j].x - mean; th = tanh_fast(fmaf(d * d, h4v, 0.25f)); q[j].x = q[j].x * fmaf(a2, th, a3);
        d = q[j].y - mean; th = tanh_fast(fmaf(d * d, h4v, 0.25f)); q[j].y = q[j].y * fmaf(a2, th, a3);
        d = q[j].z - mean; th = tanh_fast(fmaf(d * d, h4v, 0.25f)); q[j].z = q[j].z * fmaf(a2, th, a3);
        d = q[j].w - mean; th = tanh_fast(fmaf(d * d, h4v, 0.25f)); q[j].w = q[j].w * fmaf(a2, th, a3);
    }

#pragma unroll
    for (int j = 0; j < 4; j++) __stcs(&ow[t + j * 256], q[j]);
}

// ---------------------------------------------------------------------------
extern "C" void kernel_launch(void* const* d_in, const int* in_sizes, int n_in,
                              void* d_out, int out_size)
{
    const float* x  = (const float*)d_in[0];   // [B, C, H, W]
    const float* cw = (const float*)d_in[1];   // [1, 1, 5]
    const float* w1 = (const float*)d_in[2];   // [HID, C]
    const float* w2 = (const float*)d_in[3];   // [C, HID]
    float* out = (float*)d_out;

    for (int k = 0; k < NCHUNK; k++) {
        const int b0 = k * CHUNK_B;
        stat_kernel<<<RPC_, 256>>>(x, b0);
        gate_kernel<<<CHUNK_B, 256>>>(cw, w1, w2, b0);
        out_kernel<<<RPC_, 256>>>(x, out, b0);
    }
}

// round 13
// speedup vs baseline: 6.8383x; 1.2870x over previous
#include <cuda_runtime.h>

#define B_   32
#define C_   256
#define H_   64
#define W_   64
#define HW_  4096            // H*W
#define BC_  8192            // B*C
#define HID_ 64
#define KSZ_ 5

// Scratch (allocation-free rule: __device__ globals)
__device__ float g_mean[BC_];
__device__ float g_h4v[BC_];    // 0.125 / (var + 1e-4)
__device__ float g_s2[BC_];     // sum over HW of x*sigmoid(energy)
__device__ float g_gate[BC_];   // ECA gate
__device__ float g_alpha[BC_];  // fusion gate

__device__ __forceinline__ float sigm(float v) {          // tiny gate math only
    return 1.0f / (1.0f + __expf(-v));
}
__device__ __forceinline__ float tanh_fast(float v) {     // MUFU.TANH, 1 MUFU
    float r;
    asm("tanh.approx.f32 %0, %1;" : "=f"(r) : "f"(v));
    return r;
}

struct F8 { float4 a, b; };    // 32-byte vector

__device__ __forceinline__ F8 unpack(unsigned long long r0, unsigned long long r1,
                                     unsigned long long r2, unsigned long long r3) {
    F8 v;
    v.a.x = __uint_as_float((unsigned)(r0));
    v.a.y = __uint_as_float((unsigned)(r0 >> 32));
    v.a.z = __uint_as_float((unsigned)(r1));
    v.a.w = __uint_as_float((unsigned)(r1 >> 32));
    v.b.x = __uint_as_float((unsigned)(r2));
    v.b.y = __uint_as_float((unsigned)(r2 >> 32));
    v.b.z = __uint_as_float((unsigned)(r3));
    v.b.w = __uint_as_float((unsigned)(r3 >> 32));
    return v;
}
__device__ __forceinline__ unsigned long long pack2(float lo, float hi) {
    return (unsigned long long)__float_as_uint(lo)
         | ((unsigned long long)__float_as_uint(hi) << 32);
}

// 32-byte load, L2 evict_last (sm_103a: v4.b64 required with the hint)
__device__ __forceinline__ F8 ldg32_evict_last(const void* p) {
    unsigned long long r0, r1, r2, r3;
    asm volatile("ld.global.L2::evict_last.v4.b64 {%0,%1,%2,%3}, [%4];"
                 : "=l"(r0), "=l"(r1), "=l"(r2), "=l"(r3) : "l"(p));
    return unpack(r0, r1, r2, r3);
}
// plain 32-byte load
__device__ __forceinline__ F8 ldg32(const void* p) {
    unsigned long long r0, r1, r2, r3;
    asm volatile("ld.global.v4.b64 {%0,%1,%2,%3}, [%4];"
                 : "=l"(r0), "=l"(r1), "=l"(r2), "=l"(r3) : "l"(p));
    return unpack(r0, r1, r2, r3);
}
// 32-byte streaming store
__device__ __forceinline__ void stg32_cs(void* p, const F8& v) {
    const unsigned long long r0 = pack2(v.a.x, v.a.y);
    const unsigned long long r1 = pack2(v.a.z, v.a.w);
    const unsigned long long r2 = pack2(v.b.x, v.b.y);
    const unsigned long long r3 = pack2(v.b.z, v.b.w);
    asm volatile("st.global.cs.v4.b64 [%0], {%1,%2,%3,%4};"
                 :: "l"(p), "l"(r0), "l"(r1), "l"(r2), "l"(r3) : "memory");
}

// ---------------------------------------------------------------------------
// Kernel 1: per-(b,c) stats + SimAM-weighted sum.
// 16 floats/thread via 2x32B loads, register-cached across the barrier.
// ---------------------------------------------------------------------------
__global__ void __launch_bounds__(256, 8) stat_kernel(const float* __restrict__ x)
{
    const int row = blockIdx.x;                    // b*C + c
    const int t   = threadIdx.x;
    const float* xr = x + (size_t)row * HW_;

    F8 v[2];
#pragma unroll
    for (int j = 0; j < 2; j++) v[j] = ldg32_evict_last(xr + t * 8 + j * 2048);

    float s = 0.f, ss = 0.f;
#pragma unroll
    for (int j = 0; j < 2; j++) {
        float4 q = v[j].a;
        s  += (q.x + q.y) + (q.z + q.w);
        ss += q.x * q.x + q.y * q.y + q.z * q.z + q.w * q.w;
        q = v[j].b;
        s  += (q.x + q.y) + (q.z + q.w);
        ss += q.x * q.x + q.y * q.y + q.z * q.z + q.w * q.w;
    }
#pragma unroll
    for (int o = 16; o > 0; o >>= 1) {
        s  += __shfl_xor_sync(0xffffffffu, s,  o);
        ss += __shfl_xor_sync(0xffffffffu, ss, o);
    }

    __shared__ float shS[8], shQ[8], bcast[2];
    const int w = t >> 5, l = t & 31;
    if (l == 0) { shS[w] = s; shQ[w] = ss; }
    __syncthreads();
    if (t == 0) {
        float S = 0.f, Q = 0.f;
#pragma unroll
        for (int i = 0; i < 8; i++) { S += shS[i]; Q += shQ[i]; }
        const float mean = S * (1.0f / HW_);
        const float var  = (Q - (float)HW_ * mean * mean) * (1.0f / (HW_ - 1));
        const float h4v  = 0.125f / (var + 1e-4f);   // = 0.5 * 1/(4(var+eps))
        bcast[0] = mean; bcast[1] = h4v;
        g_mean[row] = mean;
        g_h4v[row]  = h4v;
    }
    __syncthreads();
    const float mean = bcast[0];
    const float h4v  = bcast[1];

    float s2 = 0.f;
#pragma unroll
    for (int j = 0; j < 2; j++) {
        float d, th;
        float4 q = v[j].a;
        d = q.x - mean; th = tanh_fast(fmaf(d * d, h4v, 0.25f)); s2 = fmaf(q.x, fmaf(th, 0.5f, 0.5f), s2);
        d = q.y - mean; th = tanh_fast(fmaf(d * d, h4v, 0.25f)); s2 = fmaf(q.y, fmaf(th, 0.5f, 0.5f), s2);
        d = q.z - mean; th = tanh_fast(fmaf(d * d, h4v, 0.25f)); s2 = fmaf(q.z, fmaf(th, 0.5f, 0.5f), s2);
        d = q.w - mean; th = tanh_fast(fmaf(d * d, h4v, 0.25f)); s2 = fmaf(q.w, fmaf(th, 0.5f, 0.5f), s2);
        q = v[j].b;
        d = q.x - mean; th = tanh_fast(fmaf(d * d, h4v, 0.25f)); s2 = fmaf(q.x, fmaf(th, 0.5f, 0.5f), s2);
        d = q.y - mean; th = tanh_fast(fmaf(d * d, h4v, 0.25f)); s2 = fmaf(q.y, fmaf(th, 0.5f, 0.5f), s2);
        d = q.z - mean; th = tanh_fast(fmaf(d * d, h4v, 0.25f)); s2 = fmaf(q.z, fmaf(th, 0.5f, 0.5f), s2);
        d = q.w - mean; th = tanh_fast(fmaf(d * d, h4v, 0.25f)); s2 = fmaf(q.w, fmaf(th, 0.5f, 0.5f), s2);
    }
#pragma unroll
    for (int o = 16; o > 0; o >>= 1)
        s2 += __shfl_xor_sync(0xffffffffu, s2, o);
    if (l == 0) shS[w] = s2;
    __syncthreads();
    if (t == 0) {
        float S = 0.f;
#pragma unroll
        for (int i = 0; i < 8; i++) S += shS[i];
        g_s2[row] = S;
    }
}

// ---------------------------------------------------------------------------
// Kernel 2: per-batch ECA conv + fusion MLP (tiny). One CTA per batch.
// ---------------------------------------------------------------------------
__global__ void __launch_bounds__(256) gate_kernel(const float* __restrict__ cw,
                                                   const float* __restrict__ w1,
                                                   const float* __restrict__ w2)
{
    const int b = blockIdx.x;
    const int c = threadIdx.x;        // 0..255
    const int idx = b * C_ + c;

    __shared__ float m[C_], gap[C_], hid[HID_];
    m[c] = g_mean[idx];
    __syncthreads();

    // ECA: cross-correlation over channel dim, zero-padded, K=5
    float y = 0.f;
#pragma unroll
    for (int k = 0; k < KSZ_; k++) {
        const int cc = c + k - (KSZ_ - 1) / 2;
        const float mv = (cc >= 0 && cc < C_) ? m[cc] : 0.f;
        y = fmaf(mv, cw[k], y);
    }
    const float gate = sigm(y);
    g_gate[idx] = gate;
    gap[c] = fmaf(gate, m[c], g_s2[idx] * (1.0f / HW_));
    __syncthreads();

    // hid[j] = relu(sum_c gap[c] * w1[j, c]); 4 threads per output j
    {
        const int j = c >> 2;          // 0..63
        const int p = c & 3;           // 0..3
        float h = 0.f;
        const float* w1r = w1 + j * C_ + p * 64;
        const float* gp  = gap + p * 64;
#pragma unroll 8
        for (int i = 0; i < 64; i++) h = fmaf(gp[i], w1r[i], h);
        h += __shfl_xor_sync(0xffffffffu, h, 1);
        h += __shfl_xor_sync(0xffffffffu, h, 2);
        if (p == 0) hid[j] = fmaxf(h, 0.f);
    }
    __syncthreads();

    // alpha[c] = sigmoid(sum_j hid[j] * w2[c, j]), w2 is [C, HID] row-major
    float a = 0.f;
    const float* w2r = w2 + c * HID_;
#pragma unroll 8
    for (int j = 0; j < HID_; j++) a = fmaf(hid[j], w2r[j], a);
    g_alpha[idx] = sigm(a);
}

// ---------------------------------------------------------------------------
// Kernel 3: out = x * (alpha*sigmoid(energy) + (1-alpha)*gate)
// 16 floats/thread via 2x32B loads and 2x32B streaming stores.
// ---------------------------------------------------------------------------
__global__ void __launch_bounds__(256, 8) out_kernel(const float* __restrict__ x,
                                                     float* __restrict__ out)
{
    const int row = BC_ - 1 - blockIdx.x;
    const int t   = threadIdx.x;

    const float mean  = g_mean[row];
    const float h4v   = g_h4v[row];
    const float alpha = g_alpha[row];
    const float a2    = 0.5f * alpha;
    const float a3    = fmaf(1.0f - alpha, g_gate[row], a2);

    const float* xr = x   + (size_t)row * HW_;
    float*       ow = out + (size_t)row * HW_;

    F8 v[2];
#pragma unroll
    for (int j = 0; j < 2; j++) v[j] = ldg32(xr + t * 8 + j * 2048);

#pragma unroll
    for (int j = 0; j < 2; j++) {
        float d, th;
        d = v[j].a.x - mean; th = tanh_fast(fmaf(d * d, h4v, 0.25f)); v[j].a.x *= fmaf(a2, th, a3);
        d = v[j].a.y - mean; th = tanh_fast(fmaf(d * d, h4v, 0.25f)); v[j].a.y *= fmaf(a2, th, a3);
        d = v[j].a.z - mean; th = tanh_fast(fmaf(d * d, h4v, 0.25f)); v[j].a.z *= fmaf(a2, th, a3);
        d = v[j].a.w - mean; th = tanh_fast(fmaf(d * d, h4v, 0.25f)); v[j].a.w *= fmaf(a2, th, a3);
        d = v[j].b.x - mean; th = tanh_fast(fmaf(d * d, h4v, 0.25f)); v[j].b.x *= fmaf(a2, th, a3);
        d = v[j].b.y - mean; th = tanh_fast(fmaf(d * d, h4v, 0.25f)); v[j].b.y *= fmaf(a2, th, a3);
        d = v[j].b.z - mean; th = tanh_fast(fmaf(d * d, h4v, 0.25f)); v[j].b.z *= fmaf(a2, th, a3);
        d = v[j].b.w - mean; th = tanh_fast(fmaf(d * d, h4v, 0.25f)); v[j].b.w *= fmaf(a2, th, a3);
    }

#pragma unroll
    for (int j = 0; j < 2; j++) stg32_cs(ow + t * 8 + j * 2048, v[j]);
}

// ---------------------------------------------------------------------------
extern "C" void kernel_launch(void* const* d_in, const int* in_sizes, int n_in,
                              void* d_out, int out_size)
{
    const float* x  = (const float*)d_in[0];   // [B, C, H, W]
    const float* cw = (const float*)d_in[1];   // [1, 1, 5]
    const float* w1 = (const float*)d_in[2];   // [HID, C]
    const float* w2 = (const float*)d_in[3];   // [C, HID]
    float* out = (float*)d_out;

    stat_kernel<<<BC_, 256>>>(x);
    gate_kernel<<<B_, 256>>>(cw, w1, w2);
    out_kernel<<<BC_, 256>>>(x, out);
}